// round 1
// baseline (speedup 1.0000x reference)
#include <cuda_runtime.h>

#define NN 50000
#define NE 600000
#define FD 128          // feature width for both aggregations / hidden
#define OUTC 64

// Scratch (static __device__ globals — allocation-free per harness rules)
__device__ float g_deg[NN];
__device__ float g_dis[NN];
__device__ float g_buf[(size_t)NN * FD];   // aggregation buffer (reused layer1+layer2)
__device__ float g_h[(size_t)NN * FD];     // hidden activations

// ---------------------------------------------------------------------------
// deg[i] = 1 + sum_{e: col=c, row!=col} w[e]
// ---------------------------------------------------------------------------
__global__ void k_deg_init() {
    int i = blockIdx.x * blockDim.x + threadIdx.x;
    if (i < NN) g_deg[i] = 1.0f;
}

__global__ void k_deg_edges(const int* __restrict__ row, const int* __restrict__ col,
                            const float* __restrict__ ew) {
    int e = blockIdx.x * blockDim.x + threadIdx.x;
    if (e >= NE) return;
    int r = row[e], c = col[e];
    if (r != c) atomicAdd(&g_deg[c], ew[e]);
}

__global__ void k_dis() {
    int i = blockIdx.x * blockDim.x + threadIdx.x;
    if (i < NN) g_dis[i] = rsqrtf(g_deg[i]);
}

// ---------------------------------------------------------------------------
// Self-loop init: buf[i,:] = src[i,:] / deg[i]   (dis[i]^2 = 1/deg[i])
// FROM_H selects src = g_h instead of the passed pointer.
// ---------------------------------------------------------------------------
template <bool FROM_H>
__global__ void k_selfinit(const float4* __restrict__ src_in) {
    int idx = blockIdx.x * blockDim.x + threadIdx.x;   // over NN*32 float4s
    if (idx >= NN * 32) return;
    const float4* src = FROM_H ? (const float4*)g_h : src_in;
    int i = idx >> 5;
    float d = g_dis[i];
    float d2 = d * d;
    float4 v = src[idx];
    v.x *= d2; v.y *= d2; v.z *= d2; v.w *= d2;
    ((float4*)g_buf)[idx] = v;
}

// ---------------------------------------------------------------------------
// Edge scatter: buf[col,:] += dis[row]*w*dis[col] * src[row,:]
// One warp per edge; each lane handles one float4 (16B) via red.global.add.v4
// ---------------------------------------------------------------------------
template <bool FROM_H>
__global__ void k_scatter(const float4* __restrict__ src_in,
                          const int* __restrict__ row, const int* __restrict__ col,
                          const float* __restrict__ ew) {
    int gw = (blockIdx.x * blockDim.x + threadIdx.x) >> 5;
    int lane = threadIdx.x & 31;
    if (gw >= NE) return;
    int r = __ldg(&row[gw]);
    int c = __ldg(&col[gw]);
    if (r == c) return;  // self-loops get weight 0 (add_remaining_self_loops)
    float coef = g_dis[r] * __ldg(&ew[gw]) * g_dis[c];
    const float4* src = FROM_H ? (const float4*)g_h : src_in;
    float4 v = src[(size_t)r * 32 + lane];
    float x0 = v.x * coef, x1 = v.y * coef, x2 = v.z * coef, x3 = v.w * coef;
    float* dst = g_buf + (size_t)c * FD + lane * 4;
    asm volatile("red.global.add.v4.f32 [%0], {%1,%2,%3,%4};"
                 :: "l"(dst), "f"(x0), "f"(x1), "f"(x2), "f"(x3)
                 : "memory");
}

// ---------------------------------------------------------------------------
// GEMM: out[n, j] = sum_k buf[n,k] * W[j,k]  (+bias, optional relu)
// MODE 0: W = W1[128,128], bias b1, relu, out -> g_h
// MODE 1: j<64 -> W_mu/b_mu -> outA (mu), j>=64 -> W_ls/b_ls -> outB (logstd)
// Block: 256 threads, 32 rows. Ws transposed in smem with pad 129 (conflict-free).
// ---------------------------------------------------------------------------
#define WPAD 129
#define GEMM_SMEM ((128 * WPAD + 32 * 128) * sizeof(float))

template <int MODE>
__global__ void k_gemm(const float* __restrict__ Wa, const float* __restrict__ ba,
                       const float* __restrict__ Wb, const float* __restrict__ bb,
                       float* __restrict__ outA, float* __restrict__ outB) {
    extern __shared__ float sm[];
    float* Ws = sm;                 // [128][129], Ws[k*129+j] = W[j][k]
    float* xs = sm + 128 * WPAD;    // [32][128]
    int tid = threadIdx.x;

    // Load weights (coalesced global reads, conflict-free smem writes via pad)
    for (int idx = tid; idx < 128 * 128; idx += 256) {
        int j = idx >> 7, k = idx & 127;
        float v;
        if (MODE == 0) v = Wa[idx];
        else           v = (j < 64) ? Wa[idx] : Wb[idx - 64 * 128];
        Ws[k * WPAD + j] = v;
    }

    int row0 = blockIdx.x * 32;
    int nrows = NN - row0; if (nrows > 32) nrows = 32;
    for (int idx = tid; idx < nrows * 128; idx += 256)
        xs[idx] = g_buf[(size_t)row0 * FD + idx];
    __syncthreads();

    int j = tid & 127;        // output column
    int rbase = (tid >> 7) * 16;  // 0 or 16

    float acc[16];
    #pragma unroll
    for (int r = 0; r < 16; r++) acc[r] = 0.0f;

    const float4* xs4 = (const float4*)xs;
    #pragma unroll 2
    for (int k4 = 0; k4 < 32; k4++) {
        float w0 = Ws[(k4 * 4 + 0) * WPAD + j];
        float w1 = Ws[(k4 * 4 + 1) * WPAD + j];
        float w2 = Ws[(k4 * 4 + 2) * WPAD + j];
        float w3 = Ws[(k4 * 4 + 3) * WPAD + j];
        #pragma unroll
        for (int r = 0; r < 16; r++) {
            float4 xv = xs4[(rbase + r) * 32 + k4];
            acc[r] = fmaf(xv.x, w0, acc[r]);
            acc[r] = fmaf(xv.y, w1, acc[r]);
            acc[r] = fmaf(xv.z, w2, acc[r]);
            acc[r] = fmaf(xv.w, w3, acc[r]);
        }
    }

    if (MODE == 0) {
        float bias = ba[j];
        #pragma unroll
        for (int r = 0; r < 16; r++) {
            int rowi = row0 + rbase + r;
            if (rowi < NN)
                g_h[(size_t)rowi * FD + j] = fmaxf(acc[r] + bias, 0.0f);
        }
    } else {
        float bias = (j < 64) ? ba[j] : bb[j - 64];
        float* o = (j < 64) ? outA : outB;
        int jj = (j < 64) ? j : j - 64;
        #pragma unroll
        for (int r = 0; r < 16; r++) {
            int rowi = row0 + rbase + r;
            if (rowi < NN)
                o[(size_t)rowi * OUTC + jj] = acc[r] + bias;
        }
    }
}

// ---------------------------------------------------------------------------
extern "C" void kernel_launch(void* const* d_in, const int* in_sizes, int n_in,
                              void* d_out, int out_size) {
    const float* x   = (const float*)d_in[0];
    const int*   ei  = (const int*)d_in[1];
    const float* ew  = (const float*)d_in[2];
    const float* W1  = (const float*)d_in[3];
    const float* b1  = (const float*)d_in[4];
    const float* Wmu = (const float*)d_in[5];
    const float* bmu = (const float*)d_in[6];
    const float* Wls = (const float*)d_in[7];
    const float* bls = (const float*)d_in[8];
    const int* row = ei;
    const int* col = ei + NE;

    float* mu = (float*)d_out;
    float* ls = mu + (size_t)NN * OUTC;

    cudaFuncSetAttribute(k_gemm<0>, cudaFuncAttributeMaxDynamicSharedMemorySize, GEMM_SMEM);
    cudaFuncSetAttribute(k_gemm<1>, cudaFuncAttributeMaxDynamicSharedMemorySize, GEMM_SMEM);

    int tb = 256;
    int gN   = (NN + tb - 1) / tb;
    int gE   = (NE + tb - 1) / tb;
    int gF4  = (NN * 32 + tb - 1) / tb;
    int gEw  = (NE * 32 + tb - 1) / tb;    // one warp per edge
    int gGemm = (NN + 31) / 32;

    // degrees + normalization
    k_deg_init<<<gN, tb>>>();
    k_deg_edges<<<gE, tb>>>(row, col, ew);
    k_dis<<<gN, tb>>>();

    // layer 1: Agg(x) -> GEMM W1 + relu -> h
    k_selfinit<false><<<gF4, tb>>>((const float4*)x);
    k_scatter<false><<<gEw, tb>>>((const float4*)x, row, col, ew);
    k_gemm<0><<<gGemm, tb, GEMM_SMEM>>>(W1, b1, nullptr, nullptr, nullptr, nullptr);

    // layer 2: Agg(h) -> GEMMs W_mu / W_ls -> mu, logstd
    k_selfinit<true><<<gF4, tb>>>(nullptr);
    k_scatter<true><<<gEw, tb>>>(nullptr, row, col, ew);
    k_gemm<1><<<gGemm, tb, GEMM_SMEM>>>(Wmu, bmu, Wls, bls, mu, ls);
}